// round 7
// baseline (speedup 1.0000x reference)
#include <cuda_runtime.h>
#include <cuda_bf16.h>
#include <cstdint>

#define NSEQ 2048
#define DH   64
#define NBH  32      // B*H
#define EPSM 1.928749848e-22f   // expf(-50)

static __device__ float g_l[NBH * NSEQ];

// pack2(lo, hi): low 16 bits = bf16(lo), high = bf16(hi)
__device__ __forceinline__ uint32_t pack2(float lo, float hi) {
    uint32_t r;  // PTX: first src -> high half, second -> low half
    asm("cvt.rn.bf16x2.f32 %0, %1, %2;" : "=r"(r) : "f"(hi), "f"(lo));
    return r;
}

// portable warp-level bf16 MMA, fp32 accum (sm_80+; no 'a'-arch features)
__device__ __forceinline__ void mma16816(float* c, const uint32_t* a,
                                         uint32_t b0, uint32_t b1) {
    asm volatile(
        "mma.sync.aligned.m16n8k16.row.col.f32.bf16.bf16.f32 "
        "{%0,%1,%2,%3}, {%4,%5,%6,%7}, {%8,%9}, {%0,%1,%2,%3};"
        : "+f"(c[0]), "+f"(c[1]), "+f"(c[2]), "+f"(c[3])
        : "r"(a[0]), "r"(a[1]), "r"(a[2]), "r"(a[3]), "r"(b0), "r"(b1));
}

// smem layout (bytes)
#define KSTRIDE 72                      // bf16 units per K row (pad: conflict-free)
#define KS_BYTES (128 * KSTRIDE * 2)    // 18432
#define SM_KHI   0
#define SM_KLO   18432
#define SM_CMASK 36864                  // 128 uchar
#define SM_LBUF  36992                  // 128 float
#define QK_SMEM  37504
#define STG_STRIDE 68                   // floats; staging unions with Ks region

// ---------------------------------------------------------------------------
// qk via mma.sync: E = exp(mask ? -50 : (q.k)/8), fused row-sum into g_l.
// CTA: 128 q x 128 k, 8 warps (4 row-bands x 2 col-halves), warp tile 32x64.
// ---------------------------------------------------------------------------
__global__ void __launch_bounds__(256)
qk_mma_kernel(const float* __restrict__ q, const float* __restrict__ kmat,
              const int* __restrict__ mask, float* __restrict__ attn)
{
    __shared__ __align__(16) char smem[QK_SMEM];

    const int tid  = threadIdx.x;
    const int lane = tid & 31, wid = tid >> 5;
    const int wr = wid >> 1, wc = wid & 1;        // warp row-band / col-half
    const int g  = lane >> 2, qd = lane & 3;      // fragment group / quad
    const int qt = blockIdx.x, bh = blockIdx.y, b = bh >> 4;

    // ---- prologue: Q fragments (hi/lo) in registers for the whole kernel ----
    uint32_t aHi[2][4][4], aLo[2][4][4];
    {
        const float* qbase = q + ((size_t)bh * NSEQ + (size_t)qt * 128) * DH;
        #pragma unroll
        for (int mt = 0; mt < 2; ++mt) {
            const int r0 = wr * 32 + mt * 16 + g, r1 = r0 + 8;
            #pragma unroll
            for (int ks = 0; ks < 4; ++ks) {
                const int c0 = ks * 16 + qd * 2;
                float2 x00 = *(const float2*)(qbase + r0 * DH + c0);
                float2 x10 = *(const float2*)(qbase + r1 * DH + c0);
                float2 x01 = *(const float2*)(qbase + r0 * DH + c0 + 8);
                float2 x11 = *(const float2*)(qbase + r1 * DH + c0 + 8);
                float h;
                h = __bfloat162float(__float2bfloat16(x00.x));
                float h2 = __bfloat162float(__float2bfloat16(x00.y));
                aHi[mt][ks][0] = pack2(h, h2);
                aLo[mt][ks][0] = pack2(x00.x - h, x00.y - h2);
                h  = __bfloat162float(__float2bfloat16(x10.x));
                h2 = __bfloat162float(__float2bfloat16(x10.y));
                aHi[mt][ks][1] = pack2(h, h2);
                aLo[mt][ks][1] = pack2(x10.x - h, x10.y - h2);
                h  = __bfloat162float(__float2bfloat16(x01.x));
                h2 = __bfloat162float(__float2bfloat16(x01.y));
                aHi[mt][ks][2] = pack2(h, h2);
                aLo[mt][ks][2] = pack2(x01.x - h, x01.y - h2);
                h  = __bfloat162float(__float2bfloat16(x11.x));
                h2 = __bfloat162float(__float2bfloat16(x11.y));
                aHi[mt][ks][3] = pack2(h, h2);
                aLo[mt][ks][3] = pack2(x11.x - h, x11.y - h2);
            }
        }
    }

    // row masks for this thread's 4 output rows
    bool rm[2][2];
    {
        const int* mrow = mask + b * NSEQ + qt * 128;
        #pragma unroll
        for (int mt = 0; mt < 2; ++mt) {
            rm[mt][0] = mrow[wr * 32 + mt * 16 + g] != 0;
            rm[mt][1] = mrow[wr * 32 + mt * 16 + g + 8] != 0;
        }
    }

    float lsum[2][2] = {{0.f, 0.f}, {0.f, 0.f}};
    unsigned char* cmaskA = (unsigned char*)(smem + SM_CMASK);
    float* stg = (float*)smem + wid * (16 * STG_STRIDE);  // warp staging (unions Ks)
    float* abase = attn + ((size_t)bh * NSEQ + (size_t)qt * 128) * NSEQ;
    const float* kball = kmat + (size_t)bh * NSEQ * DH;

    for (int kt = 0; kt < NSEQ / 128; ++kt) {
        __syncthreads();   // epilogue (staging in Ks union) fully consumed

        // ---- K chunk: 128 k-rows x 64 d, fp32 -> hi/lo bf16 smem ----
        {
            const int r  = tid >> 1;
            const int cc = (tid & 1) * 32;
            const float* kb = kball + (size_t)(kt * 128 + r) * DH + cc;
            char* hB = smem + SM_KHI + (size_t)r * (KSTRIDE * 2);
            char* lB = smem + SM_KLO + (size_t)r * (KSTRIDE * 2);
            #pragma unroll
            for (int c4 = 0; c4 < 32; c4 += 4) {
                float4 x = *(const float4*)(kb + c4);
                float h0 = __bfloat162float(__float2bfloat16(x.x));
                float h1 = __bfloat162float(__float2bfloat16(x.y));
                float h2 = __bfloat162float(__float2bfloat16(x.z));
                float h3 = __bfloat162float(__float2bfloat16(x.w));
                *(uint32_t*)(hB + (cc + c4) * 2)     = pack2(h0, h1);
                *(uint32_t*)(hB + (cc + c4 + 2) * 2) = pack2(h2, h3);
                *(uint32_t*)(lB + (cc + c4) * 2)     = pack2(x.x - h0, x.y - h1);
                *(uint32_t*)(lB + (cc + c4 + 2) * 2) = pack2(x.z - h2, x.w - h3);
            }
        }
        if (tid < 128)
            cmaskA[tid] = (unsigned char)(mask[b * NSEQ + kt * 128 + tid] != 0);
        __syncthreads();

        // ---- MMA: 8 n-tiles x 4 k-steps x 3 products x 2 m-tiles ----
        float acc[2][8][4];
        #pragma unroll
        for (int mt = 0; mt < 2; ++mt)
            #pragma unroll
            for (int nt = 0; nt < 8; ++nt)
                #pragma unroll
                for (int u = 0; u < 4; ++u) acc[mt][nt][u] = 0.f;

        #pragma unroll
        for (int nt = 0; nt < 8; ++nt) {
            const int nrow = wc * 64 + nt * 8 + g;
            const char* krH = smem + SM_KHI + (size_t)nrow * (KSTRIDE * 2);
            const char* krL = smem + SM_KLO + (size_t)nrow * (KSTRIDE * 2);
            #pragma unroll
            for (int ks = 0; ks < 4; ++ks) {
                const int koff = (ks * 16 + qd * 2) * 2;
                uint32_t bh0 = *(const uint32_t*)(krH + koff);
                uint32_t bh1 = *(const uint32_t*)(krH + koff + 16);
                uint32_t bl0 = *(const uint32_t*)(krL + koff);
                uint32_t bl1 = *(const uint32_t*)(krL + koff + 16);
                #pragma unroll
                for (int mt = 0; mt < 2; ++mt) {
                    mma16816(acc[mt][nt], aHi[mt][ks], bh0, bh1);
                    mma16816(acc[mt][nt], aHi[mt][ks], bl0, bl1);
                    mma16816(acc[mt][nt], aLo[mt][ks], bh0, bh1);
                }
            }
        }
        __syncthreads();   // all warps done reading Ks before staging overwrites

        // ---- epilogue: exp + mask + row-sum + coalesced store via staging ----
        #pragma unroll
        for (int mt = 0; mt < 2; ++mt) {
            #pragma unroll
            for (int nt = 0; nt < 8; ++nt) {
                const int col0 = nt * 8 + qd * 2;
                const uint16_t mm = *(const uint16_t*)(cmaskA + wc * 64 + col0);
                const bool m0 = (mm & 0xffu) != 0, m1 = (mm >> 8) != 0;
                float* c = acc[mt][nt];
                float e0 = (rm[mt][0] || m0) ? EPSM : __expf(c[0] * 0.125f);
                float e1 = (rm[mt][0] || m1) ? EPSM : __expf(c[1] * 0.125f);
                float e2 = (rm[mt][1] || m0) ? EPSM : __expf(c[2] * 0.125f);
                float e3 = (rm[mt][1] || m1) ? EPSM : __expf(c[3] * 0.125f);
                lsum[mt][0] += e0 + e1;
                lsum[mt][1] += e2 + e3;
                *(float2*)(stg + g * STG_STRIDE + col0)       = make_float2(e0, e1);
                *(float2*)(stg + (g + 8) * STG_STRIDE + col0) = make_float2(e2, e3);
            }
            __syncwarp();
            // coalesced 16-row x 64-col store (2 lanes per row, 128B each)
            {
                const int sr  = lane >> 1;
                const int scc = (lane & 1) * 32;
                float* dst = abase
                    + (size_t)(wr * 32 + mt * 16 + sr) * NSEQ
                    + kt * 128 + wc * 64 + scc;
                const float* src = stg + sr * STG_STRIDE + scc;
                #pragma unroll
                for (int j = 0; j < 32; j += 4)
                    *(float4*)(dst + j) = *(const float4*)(src + j);
            }
            __syncwarp();
        }
    }

    // ---- final row-sum reduce: quad shfl, then combine the two col-halves ----
    #pragma unroll
    for (int mt = 0; mt < 2; ++mt)
        #pragma unroll
        for (int h = 0; h < 2; ++h) {
            float s = lsum[mt][h];
            s += __shfl_xor_sync(0xffffffffu, s, 1);
            s += __shfl_xor_sync(0xffffffffu, s, 2);
            lsum[mt][h] = s;
        }
    float* lbuf = (float*)(smem + SM_LBUF);
    __syncthreads();
    if (wc == 1 && qd == 0) {
        #pragma unroll
        for (int mt = 0; mt < 2; ++mt) {
            lbuf[wr * 32 + mt * 16 + g]     = lsum[mt][0];
            lbuf[wr * 32 + mt * 16 + g + 8] = lsum[mt][1];
        }
    }
    __syncthreads();
    if (wc == 0 && qd == 0) {
        #pragma unroll
        for (int mt = 0; mt < 2; ++mt) {
            const int r0 = wr * 32 + mt * 16 + g;
            g_l[bh * NSEQ + qt * 128 + r0]     = lsum[mt][0] + lbuf[r0];
            g_l[bh * NSEQ + qt * 128 + r0 + 8] = lsum[mt][1] + lbuf[r0 + 8];
        }
    }
}

// ---------------------------------------------------------------------------
// pv (scalar, round-4): p = E / l (written back as attn), O = P.V
// ---------------------------------------------------------------------------
__global__ __launch_bounds__(128) void pv_kernel(
    const float* __restrict__ v, float* __restrict__ attn,
    float* __restrict__ out)
{
    __shared__ float Ps[128 * 36];
    __shared__ float Vs[32 * 68];

    const int qt  = blockIdx.x;
    const int bh  = blockIdx.y;
    const int tid = threadIdx.x;
    const int tx  = tid & 7;
    const int ty  = tid >> 3;

    const int sc  = (tid & 7) * 4;
    const int sr0 = tid >> 3;
    const int vr  = tid >> 2;
    const int vc  = (tid & 3) * 16;

    float rlv[8];
    #pragma unroll
    for (int i = 0; i < 8; ++i)
        rlv[i] = 1.f / g_l[bh * NSEQ + qt * 128 + sr0 + 16 * i];

    float* abase = attn + ((size_t)bh * NSEQ + (size_t)qt * 128) * NSEQ;
    const float* vbase = v + (size_t)bh * NSEQ * DH;

    float4 eReg[8];
    float4 vReg[4];
    #pragma unroll
    for (int i = 0; i < 8; ++i)
        eReg[i] = *(const float4*)(abase + (size_t)(sr0 + 16 * i) * NSEQ + sc);
    #pragma unroll
    for (int j = 0; j < 4; ++j)
        vReg[j] = *(const float4*)(vbase + (size_t)vr * DH + vc + 4 * j);

    float acc[8][8];
    #pragma unroll
    for (int i = 0; i < 8; ++i)
        #pragma unroll
        for (int j = 0; j < 8; ++j) acc[i][j] = 0.f;

    for (int kt = 0; kt < NSEQ / 32; ++kt) {
        __syncthreads();
        #pragma unroll
        for (int i = 0; i < 8; ++i) {
            const int r = sr0 + 16 * i;
            const float s = rlv[i];
            float4 p4 = make_float4(eReg[i].x * s, eReg[i].y * s,
                                    eReg[i].z * s, eReg[i].w * s);
            *(float4*)(abase + (size_t)r * NSEQ + kt * 32 + sc) = p4;
            *(float4*)&Ps[r * 36 + sc] = p4;
        }
        #pragma unroll
        for (int j = 0; j < 4; ++j)
            *(float4*)&Vs[vr * 68 + vc + 4 * j] = vReg[j];
        __syncthreads();

        if (kt + 1 < NSEQ / 32) {
            const float* ebp = abase + (kt + 1) * 32 + sc;
            #pragma unroll
            for (int i = 0; i < 8; ++i)
                eReg[i] = *(const float4*)(ebp + (size_t)(sr0 + 16 * i) * NSEQ);
            const float* vbp = vbase + (size_t)((kt + 1) * 32 + vr) * DH + vc;
            #pragma unroll
            for (int j = 0; j < 4; ++j)
                vReg[j] = *(const float4*)(vbp + 4 * j);
        }

        #pragma unroll
        for (int k0 = 0; k0 < 32; k0 += 4) {
            float Pfa[8][4];
            #pragma unroll
            for (int i = 0; i < 8; ++i) {
                const int r = ((i >> 2) * 64) + ty * 4 + (i & 3);
                float4 t = *(const float4*)&Ps[r * 36 + k0];
                Pfa[i][0] = t.x; Pfa[i][1] = t.y; Pfa[i][2] = t.z; Pfa[i][3] = t.w;
            }
            #pragma unroll
            for (int kk = 0; kk < 4; ++kk) {
                float4 v0 = *(const float4*)&Vs[(k0 + kk) * 68 + tx * 4];
                float4 v1 = *(const float4*)&Vs[(k0 + kk) * 68 + 32 + tx * 4];
                float bv[8] = {v0.x, v0.y, v0.z, v0.w, v1.x, v1.y, v1.z, v1.w};
                #pragma unroll
                for (int i = 0; i < 8; ++i)
                    #pragma unroll
                    for (int j = 0; j < 8; ++j)
                        acc[i][j] += Pfa[i][kk] * bv[j];
            }
        }
    }

    float* obase = out + ((size_t)bh * NSEQ + (size_t)qt * 128) * DH;
    #pragma unroll
    for (int i = 0; i < 8; ++i) {
        const int row = ((i >> 2) * 64) + ty * 4 + (i & 3);
        *(float4*)(obase + (size_t)row * DH + tx * 4)
            = make_float4(acc[i][0], acc[i][1], acc[i][2], acc[i][3]);
        *(float4*)(obase + (size_t)row * DH + 32 + tx * 4)
            = make_float4(acc[i][4], acc[i][5], acc[i][6], acc[i][7]);
    }
}

extern "C" void kernel_launch(void* const* d_in, const int* in_sizes, int n_in,
                              void* d_out, int out_size)
{
    const float* q    = (const float*)d_in[0];
    const float* kmat = (const float*)d_in[1];
    const float* v    = (const float*)d_in[2];
    const int*   mask = (const int*)d_in[3];

    float* out  = (float*)d_out;                  // [B,H,N,D] first (tuple order)
    float* attn = out + (size_t)NBH * NSEQ * DH;  // [B,H,N,N] second

    qk_mma_kernel<<<dim3(NSEQ / 128, NBH), 256>>>(q, kmat, mask, attn);
    pv_kernel<<<dim3(NSEQ / 128, NBH), 128>>>(v, attn, out);
}